// round 2
// baseline (speedup 1.0000x reference)
#include <cuda_runtime.h>
#include <cstdint>

#define N_NODES_MAX 50000
#define D 128

// Scratch accumulator for segment_sum (allocation-free rule: __device__ global)
__device__ float g_nbr_sum[(size_t)N_NODES_MAX * D];
// Index dtype flag: 1 if edge_index is int64, 0 if int32
__device__ int g_is64;

// ---------------------------------------------------------------------------
// Kernel 0: sniff index dtype. JAX default x64-disabled => int32 expected,
// but detect robustly: int64 non-negative values < 2^31 have zero high words
// at every odd int32 slot.
// ---------------------------------------------------------------------------
__global__ void sniff_kernel(const unsigned* __restrict__ raw) {
    int all_zero = 1;
    #pragma unroll 1
    for (int i = 1; i < 256; i += 2) {
        if (raw[i] != 0u) { all_zero = 0; break; }
    }
    g_is64 = all_zero;
}

// ---------------------------------------------------------------------------
// Kernel 1: zero the accumulator
// ---------------------------------------------------------------------------
__global__ void zero_kernel(int n_float4) {
    int i = blockIdx.x * blockDim.x + threadIdx.x;
    if (i < n_float4) {
        ((float4*)g_nbr_sum)[i] = make_float4(0.f, 0.f, 0.f, 0.f);
    }
}

// ---------------------------------------------------------------------------
// Kernel 2: edge scatter. One warp per edge; each lane moves one float4.
//   nbr_sum[src] += node_feats[dst]
// Vectorized red.global.add.v4.f32 (sm_90+) quarters the atomic op count.
// ---------------------------------------------------------------------------
__global__ void scatter_kernel(const float* __restrict__ X,
                               const void* __restrict__ ei_raw,
                               int n_edges) {
    int t = blockIdx.x * blockDim.x + threadIdx.x;
    int e = t >> 5;
    int lane = t & 31;
    if (e >= n_edges) return;

    long long src, dst;
    if (g_is64) {
        const long long* ei = (const long long*)ei_raw;
        src = ei[e];
        dst = ei[n_edges + e];
    } else {
        const int* ei = (const int*)ei_raw;
        src = ei[e];
        dst = ei[n_edges + e];
    }

    float4 v = __ldg((const float4*)(X + dst * D) + lane);
    float* p = g_nbr_sum + src * D + lane * 4;
    asm volatile("red.global.add.v4.f32 [%0], {%1, %2, %3, %4};"
                 :: "l"(p), "f"(v.x), "f"(v.y), "f"(v.z), "f"(v.w)
                 : "memory");
}

// ---------------------------------------------------------------------------
// Kernel 3: fused dual GEMM + tanh epilogue.
//   out = X @ Ws + tanh(S @ Wn + b)
// Classic 128x128 tile, BK=16, 256 threads, 8x8 register micro-tile.
// Two K-passes share ONE accumulator set: pass0 computes S@Wn, then
// acc = tanh(acc + b), then pass1 keeps accumulating X@Ws into the same regs.
// ---------------------------------------------------------------------------
#define BM 128
#define BN 128
#define BK 16
#define TM 8
#define TN 8

__global__ __launch_bounds__(256, 2)
void fused_gemm_kernel(const float* __restrict__ X,
                       const float* __restrict__ Ws,
                       const float* __restrict__ Wn,
                       const float* __restrict__ bias,
                       float* __restrict__ out,
                       int M) {
    __shared__ float As[BK][BM];   // A tile, transposed: As[k][m]
    __shared__ float Bs[BK][BN];   // W tile: Bs[k][n]

    const int m0   = blockIdx.x * BM;
    const int tid  = threadIdx.x;
    const int tcol = tid & 15;     // 0..15 -> output cols tcol*8 .. +7
    const int trow = tid >> 4;     // 0..15 -> output rows trow*8 .. +7

    float acc[TM][TN];
    #pragma unroll
    for (int i = 0; i < TM; i++)
        #pragma unroll
        for (int j = 0; j < TN; j++) acc[i][j] = 0.f;

    const float* S = g_nbr_sum;

    #pragma unroll
    for (int pass = 0; pass < 2; pass++) {
        const float* Aptr = (pass == 0) ? S  : X;
        const float* Wptr = (pass == 0) ? Wn : Ws;

        for (int k0 = 0; k0 < D; k0 += BK) {
            __syncthreads();  // protect smem from previous iter's readers
            // --- load A tile (128 rows x 16 k) and B tile (16 k x 128 cols)
            #pragma unroll
            for (int l = 0; l < 2; l++) {
                int v = tid + l * 256;          // 0..511 float4 slots
                // A: 4 float4 per row of 16 floats
                int arow = v >> 2;
                int ac4  = v & 3;
                int gr   = m0 + arow;
                if (gr > M - 1) gr = M - 1;     // clamp (safe; rows unused)
                float4 av = __ldg((const float4*)(Aptr + (size_t)gr * D + k0) + ac4);
                As[ac4 * 4 + 0][arow] = av.x;
                As[ac4 * 4 + 1][arow] = av.y;
                As[ac4 * 4 + 2][arow] = av.z;
                As[ac4 * 4 + 3][arow] = av.w;
                // B: 32 float4 per k-row of 128 floats
                int brow = v >> 5;
                int bc4  = v & 31;
                float4 bv = __ldg((const float4*)(Wptr + (size_t)(k0 + brow) * D) + bc4);
                *(float4*)&Bs[brow][bc4 * 4] = bv;
            }
            __syncthreads();

            // --- compute
            #pragma unroll
            for (int kk = 0; kk < BK; kk++) {
                float a_frag[TM], b_frag[TN];
                *(float4*)&a_frag[0] = *(const float4*)&As[kk][trow * TM];
                *(float4*)&a_frag[4] = *(const float4*)&As[kk][trow * TM + 4];
                *(float4*)&b_frag[0] = *(const float4*)&Bs[kk][tcol * TN];
                *(float4*)&b_frag[4] = *(const float4*)&Bs[kk][tcol * TN + 4];
                #pragma unroll
                for (int i = 0; i < TM; i++)
                    #pragma unroll
                    for (int j = 0; j < TN; j++)
                        acc[i][j] = fmaf(a_frag[i], b_frag[j], acc[i][j]);
            }
        }

        if (pass == 0) {
            // epilogue of GEMM 1: acc = tanh(acc + b[col])
            float bj[TN];
            #pragma unroll
            for (int j = 0; j < TN; j++) bj[j] = __ldg(bias + tcol * TN + j);
            #pragma unroll
            for (int i = 0; i < TM; i++)
                #pragma unroll
                for (int j = 0; j < TN; j++)
                    acc[i][j] = tanhf(acc[i][j] + bj[j]);
        }
    }

    // --- write out (rows may exceed M in the last block)
    #pragma unroll
    for (int i = 0; i < TM; i++) {
        int row = m0 + trow * TM + i;
        if (row < M) {
            float4* o = (float4*)(out + (size_t)row * D + tcol * TN);
            o[0] = make_float4(acc[i][0], acc[i][1], acc[i][2], acc[i][3]);
            o[1] = make_float4(acc[i][4], acc[i][5], acc[i][6], acc[i][7]);
        }
    }
}

// ---------------------------------------------------------------------------
// Launch
// ---------------------------------------------------------------------------
extern "C" void kernel_launch(void* const* d_in, const int* in_sizes, int n_in,
                              void* d_out, int out_size) {
    const float* X   = (const float*)d_in[0];   // [N, 128]
    const void*  ei  = d_in[1];                 // [2, E] int32 or int64
    const float* Wn  = (const float*)d_in[2];   // nbr_w [128,128]
    const float* Ws  = (const float*)d_in[3];   // self_w [128,128]
    const float* b   = (const float*)d_in[4];   // [128]
    float*       out = (float*)d_out;

    const int M = in_sizes[0] / D;       // 50000
    const int E = in_sizes[1] / 2;       // 800000

    // 0) detect index dtype (device-side, graph-capturable)
    sniff_kernel<<<1, 1>>>((const unsigned*)ei);

    // 1) zero accumulator
    int n_f4 = (M * D) / 4;
    zero_kernel<<<(n_f4 + 255) / 256, 256>>>(n_f4);

    // 2) edge scatter (1 warp per edge)
    long long scatter_threads = (long long)E * 32;
    int scatter_blocks = (int)((scatter_threads + 255) / 256);
    scatter_kernel<<<scatter_blocks, 256>>>(X, ei, E);

    // 3) fused dual GEMM + tanh
    int gemm_blocks = (M + BM - 1) / BM;
    fused_gemm_kernel<<<gemm_blocks, 256>>>(X, Ws, Wn, b, out, M);
}

// round 3
// speedup vs baseline: 1.1296x; 1.1296x over previous
#include <cuda_runtime.h>
#include <cstdint>

#define D 128
#define N_NODES_MAX 50000

// Scratch accumulator for segment_sum (allocation-free rule: __device__ global)
__device__ float g_nbr_sum[(size_t)N_NODES_MAX * D];
// Index dtype flag: 1 if edge_index is int64, 0 if int32
__device__ int g_is64;

// ---------------------------------------------------------------------------
// Kernel 0: sniff index dtype (int64 non-neg < 2^31 => all odd u32 words zero)
// ---------------------------------------------------------------------------
__global__ void sniff_kernel(const unsigned* __restrict__ raw) {
    int all_zero = 1;
    #pragma unroll 1
    for (int i = 1; i < 256; i += 2) {
        if (raw[i] != 0u) { all_zero = 0; break; }
    }
    g_is64 = all_zero;
}

// ---------------------------------------------------------------------------
// Kernel 1: zero the accumulator
// ---------------------------------------------------------------------------
__global__ void zero_kernel(int n_float4) {
    int i = blockIdx.x * blockDim.x + threadIdx.x;
    if (i < n_float4) {
        ((float4*)g_nbr_sum)[i] = make_float4(0.f, 0.f, 0.f, 0.f);
    }
}

// ---------------------------------------------------------------------------
// Phase 1: block-interleaved  (a) edge scatter  (b) self GEMM out = X @ Ws
// Scatter: each warp owns 16 edges; indices coalesced-loaded once and
// shfl-distributed; gathers batched 8-deep (MLP=8) before the vector reds.
// Self GEMM: proven SIMT 128x128xBK16 tile, 8x8 micro-tile (FFMA roofline).
// ---------------------------------------------------------------------------
#define BM 128
#define BN 128
#define BK 16
#define TM 8
#define TN 8

__global__ __launch_bounds__(256, 2)
void phase1_kernel(const float* __restrict__ X,
                   const float* __restrict__ Ws,
                   const void*  __restrict__ ei_raw,
                   float* __restrict__ out,
                   int M, int E, int G /* #gemm blocks */) {
    const int bid = blockIdx.x;
    const int q = bid >> 4, r = bid & 15;
    const bool isGemm = (r == 8) && (q < G);

    if (!isGemm) {
        // ------------------------- scatter path ---------------------------
        const int nGbefore = min(q + (r > 8 ? 1 : 0), G);
        const int sid = bid - nGbefore;
        const int w = threadIdx.x >> 5;
        const int lane = threadIdx.x & 31;
        const long long e0 = ((long long)sid * 8 + w) * 16;
        if (e0 >= E) return;

        int idx;  // lanes 0..15 hold src[e0+lane], lanes 16..31 hold dst
        {
            long long pos = (lane < 16) ? (e0 + lane)
                                        : ((long long)E + e0 + (lane - 16));
            if (g_is64) idx = (int)((const long long*)ei_raw)[pos];
            else        idx = ((const int*)ei_raw)[pos];
        }
        #pragma unroll
        for (int j0 = 0; j0 < 16; j0 += 8) {
            float4 v[8];
            int s[8];
            #pragma unroll
            for (int j = 0; j < 8; j++) {
                int dj = __shfl_sync(0xffffffffu, idx, 16 + j0 + j);
                s[j]   = __shfl_sync(0xffffffffu, idx, j0 + j);
                v[j] = __ldg((const float4*)(X + (size_t)dj * D) + lane);
            }
            #pragma unroll
            for (int j = 0; j < 8; j++) {
                float* p = g_nbr_sum + (size_t)s[j] * D + lane * 4;
                asm volatile("red.global.add.v4.f32 [%0], {%1,%2,%3,%4};"
                             :: "l"(p), "f"(v[j].x), "f"(v[j].y),
                                "f"(v[j].z), "f"(v[j].w) : "memory");
            }
        }
        return;
    }

    // --------------------------- self-GEMM path ---------------------------
    __shared__ float As[BK][BM];
    __shared__ float Bs[BK][BN];

    const int m0   = q * BM;
    const int tid  = threadIdx.x;
    const int tcol = tid & 15;
    const int trow = tid >> 4;

    float acc[TM][TN];
    #pragma unroll
    for (int i = 0; i < TM; i++)
        #pragma unroll
        for (int j = 0; j < TN; j++) acc[i][j] = 0.f;

    for (int k0 = 0; k0 < D; k0 += BK) {
        __syncthreads();
        #pragma unroll
        for (int l = 0; l < 2; l++) {
            int v = tid + l * 256;
            int arow = v >> 2;
            int ac4  = v & 3;
            int gr   = m0 + arow;
            if (gr > M - 1) gr = M - 1;
            float4 av = __ldg((const float4*)(X + (size_t)gr * D + k0) + ac4);
            As[ac4 * 4 + 0][arow] = av.x;
            As[ac4 * 4 + 1][arow] = av.y;
            As[ac4 * 4 + 2][arow] = av.z;
            As[ac4 * 4 + 3][arow] = av.w;
            int brow = v >> 5;
            int bc4  = v & 31;
            float4 bv = __ldg((const float4*)(Ws + (size_t)(k0 + brow) * D) + bc4);
            *(float4*)&Bs[brow][bc4 * 4] = bv;
        }
        __syncthreads();

        #pragma unroll
        for (int kk = 0; kk < BK; kk++) {
            float a_frag[TM], b_frag[TN];
            *(float4*)&a_frag[0] = *(const float4*)&As[kk][trow * TM];
            *(float4*)&a_frag[4] = *(const float4*)&As[kk][trow * TM + 4];
            *(float4*)&b_frag[0] = *(const float4*)&Bs[kk][tcol * TN];
            *(float4*)&b_frag[4] = *(const float4*)&Bs[kk][tcol * TN + 4];
            #pragma unroll
            for (int i = 0; i < TM; i++)
                #pragma unroll
                for (int j = 0; j < TN; j++)
                    acc[i][j] = fmaf(a_frag[i], b_frag[j], acc[i][j]);
        }
    }

    #pragma unroll
    for (int i = 0; i < TM; i++) {
        int row = m0 + trow * TM + i;
        if (row < M) {
            float4* o = (float4*)(out + (size_t)row * D + tcol * TN);
            o[0] = make_float4(acc[i][0], acc[i][1], acc[i][2], acc[i][3]);
            o[1] = make_float4(acc[i][4], acc[i][5], acc[i][6], acc[i][7]);
        }
    }
}

// ---------------------------------------------------------------------------
// Phase 2: TF32 tensor-core GEMM:  out += tanh(S @ Wn + b)
// 128x128 tile / CTA, 8 warps in 4(m) x 2(n), warp tile 32x64,
// mma.sync.m16n8k8.tf32. Inputs rounded to tf32 (cvt.rna) at smem-store time.
// ---------------------------------------------------------------------------
__device__ __forceinline__ uint32_t f2tf32(float f) {
    uint32_t u;
    asm("cvt.rna.tf32.f32 %0, %1;" : "=r"(u) : "f"(f));
    return u;
}

__global__ __launch_bounds__(256, 2)
void nbr_gemm_tf32_kernel(const float* __restrict__ Wn,
                          const float* __restrict__ bias,
                          float* __restrict__ out,
                          int M) {
    __shared__ uint32_t As[128][36];   // [m][k], pad 36 -> conflict-free frags
    __shared__ uint32_t Bs[32][136];   // [k][n], pad 136 -> conflict-free frags

    const int tid  = threadIdx.x;
    const int m0   = blockIdx.x * 128;
    const int warp = tid >> 5;
    const int lane = tid & 31;
    const int wm   = warp & 3;    // 0..3 -> m offset wm*32
    const int wn   = warp >> 2;   // 0..1 -> n offset wn*64
    const int g    = lane >> 2;   // groupID
    const int t    = lane & 3;    // threadID_in_group

    const float* S = g_nbr_sum;

    float c[2][8][4];
    #pragma unroll
    for (int im = 0; im < 2; im++)
        #pragma unroll
        for (int in_ = 0; in_ < 8; in_++)
            #pragma unroll
            for (int x = 0; x < 4; x++) c[im][in_][x] = 0.f;

    for (int k0 = 0; k0 < 128; k0 += 32) {
        __syncthreads();
        // A tile: 128 x 32  (1024 float4, 4 per thread)
        #pragma unroll
        for (int l = 0; l < 4; l++) {
            int v = tid + l * 256;
            int row = v >> 3;
            int c4  = v & 7;
            int gr  = m0 + row;
            if (gr > M - 1) gr = M - 1;
            float4 a = __ldg((const float4*)(S + (size_t)gr * 128 + k0) + c4);
            As[row][c4 * 4 + 0] = f2tf32(a.x);
            As[row][c4 * 4 + 1] = f2tf32(a.y);
            As[row][c4 * 4 + 2] = f2tf32(a.z);
            As[row][c4 * 4 + 3] = f2tf32(a.w);
        }
        // B tile: 32 x 128
        #pragma unroll
        for (int l = 0; l < 4; l++) {
            int v = tid + l * 256;
            int row = v >> 5;
            int c4  = v & 31;
            float4 b = __ldg((const float4*)(Wn + (size_t)(k0 + row) * 128) + c4);
            Bs[row][c4 * 4 + 0] = f2tf32(b.x);
            Bs[row][c4 * 4 + 1] = f2tf32(b.y);
            Bs[row][c4 * 4 + 2] = f2tf32(b.z);
            Bs[row][c4 * 4 + 3] = f2tf32(b.w);
        }
        __syncthreads();

        #pragma unroll
        for (int kk = 0; kk < 32; kk += 8) {
            uint32_t af[2][4];
            #pragma unroll
            for (int im = 0; im < 2; im++) {
                int ar = wm * 32 + im * 16 + g;
                af[im][0] = As[ar    ][kk + t];
                af[im][1] = As[ar + 8][kk + t];
                af[im][2] = As[ar    ][kk + t + 4];
                af[im][3] = As[ar + 8][kk + t + 4];
            }
            uint32_t bf[8][2];
            #pragma unroll
            for (int in_ = 0; in_ < 8; in_++) {
                int bc = wn * 64 + in_ * 8 + g;
                bf[in_][0] = Bs[kk + t    ][bc];
                bf[in_][1] = Bs[kk + t + 4][bc];
            }
            #pragma unroll
            for (int im = 0; im < 2; im++)
                #pragma unroll
                for (int in_ = 0; in_ < 8; in_++) {
                    asm volatile(
                        "mma.sync.aligned.m16n8k8.row.col.f32.tf32.tf32.f32 "
                        "{%0,%1,%2,%3}, {%4,%5,%6,%7}, {%8,%9}, {%0,%1,%2,%3};"
                        : "+f"(c[im][in_][0]), "+f"(c[im][in_][1]),
                          "+f"(c[im][in_][2]), "+f"(c[im][in_][3])
                        : "r"(af[im][0]), "r"(af[im][1]),
                          "r"(af[im][2]), "r"(af[im][3]),
                          "r"(bf[in_][0]), "r"(bf[in_][1]));
                }
        }
    }

    // Epilogue: out += tanh(c + bias)
    #pragma unroll
    for (int im = 0; im < 2; im++) {
        int r0 = m0 + wm * 32 + im * 16 + g;
        #pragma unroll
        for (int in_ = 0; in_ < 8; in_++) {
            int col = wn * 64 + in_ * 8 + 2 * t;
            float b0 = __ldg(bias + col);
            float b1 = __ldg(bias + col + 1);
            if (r0 < M) {
                float2* p = (float2*)(out + (size_t)r0 * 128 + col);
                float2 o = *p;
                o.x += tanhf(c[im][in_][0] + b0);
                o.y += tanhf(c[im][in_][1] + b1);
                *p = o;
            }
            if (r0 + 8 < M) {
                float2* p = (float2*)(out + (size_t)(r0 + 8) * 128 + col);
                float2 o = *p;
                o.x += tanhf(c[im][in_][2] + b0);
                o.y += tanhf(c[im][in_][3] + b1);
                *p = o;
            }
        }
    }
}

// ---------------------------------------------------------------------------
// Launch
// ---------------------------------------------------------------------------
extern "C" void kernel_launch(void* const* d_in, const int* in_sizes, int n_in,
                              void* d_out, int out_size) {
    const float* X   = (const float*)d_in[0];   // [N, 128]
    const void*  ei  = d_in[1];                 // [2, E] int32 or int64
    const float* Wn  = (const float*)d_in[2];   // nbr_w [128,128]
    const float* Ws  = (const float*)d_in[3];   // self_w [128,128]
    const float* b   = (const float*)d_in[4];   // [128]
    float*       out = (float*)d_out;

    const int M = in_sizes[0] / D;       // 50000
    const int E = in_sizes[1] / 2;       // 800000

    // 0) detect index dtype
    sniff_kernel<<<1, 1>>>((const unsigned*)ei);

    // 1) zero accumulator
    int n_f4 = (M * D) / 4;
    zero_kernel<<<(n_f4 + 255) / 256, 256>>>(n_f4);

    // 2) phase1: scatter (E/128 blocks) + self GEMM (G blocks), interleaved
    int G = (M + BM - 1) / BM;                 // 391
    int S_blocks = (E + 127) / 128;            // 6250
    int total = S_blocks + G;
    int min_total = 16 * (G - 1) + 9;          // ensure all gemm slots exist
    if (total < min_total) total = min_total;
    phase1_kernel<<<total, 256>>>(X, Ws, ei, out, M, E, G);

    // 3) phase2: nbr GEMM (TF32) + tanh + accumulate
    nbr_gemm_tf32_kernel<<<G, 256>>>(Wn, b, out, M);
}

// round 4
// speedup vs baseline: 1.4600x; 1.2925x over previous
#include <cuda_runtime.h>
#include <cstdint>

#define D 128
#define N_NODES_MAX 50000

__device__ float g_nbr_sum[(size_t)N_NODES_MAX * D];
__device__ int g_is64;

// ---------------------------------------------------------------------------
// Kernel 1: zero accumulator + (block 0) sniff index dtype.
// int64 non-negative < 2^31 => all odd u32 words zero across 128 samples.
// ---------------------------------------------------------------------------
__global__ void zero_sniff_kernel(const unsigned* __restrict__ raw, int n_f4) {
    int i = blockIdx.x * blockDim.x + threadIdx.x;
    if (i < n_f4) {
        ((float4*)g_nbr_sum)[i] = make_float4(0.f, 0.f, 0.f, 0.f);
    }
    if (blockIdx.x == 0) {
        __shared__ int s_nz;
        if (threadIdx.x == 0) s_nz = 0;
        __syncthreads();
        if (threadIdx.x < 128 && raw[2 * threadIdx.x + 1] != 0u) s_nz = 1;
        __syncthreads();
        if (threadIdx.x == 0) g_is64 = (s_nz == 0);
    }
}

// ---------------------------------------------------------------------------
// Kernel 2: edge scatter (standalone, full occupancy).
// Each warp owns 16 edges; indices coalesced-loaded once, shfl-distributed;
// gathers batched 8-deep (MLP=8) before vector reds.
// ---------------------------------------------------------------------------
__global__ __launch_bounds__(256)
void scatter_kernel(const float* __restrict__ X,
                    const void* __restrict__ ei_raw,
                    int E) {
    const int w = threadIdx.x >> 5;
    const int lane = threadIdx.x & 31;
    const long long e0 = ((long long)blockIdx.x * 8 + w) * 16;
    if (e0 >= E) return;

    int idx;  // lanes 0..15: src[e0+lane]; lanes 16..31: dst[e0+lane-16]
    {
        long long pos = (lane < 16) ? (e0 + lane)
                                    : ((long long)E + e0 + (lane - 16));
        if (g_is64) idx = (int)((const long long*)ei_raw)[pos];
        else        idx = ((const int*)ei_raw)[pos];
    }
    #pragma unroll
    for (int j0 = 0; j0 < 16; j0 += 8) {
        float4 v[8];
        int s[8];
        #pragma unroll
        for (int j = 0; j < 8; j++) {
            int dj = __shfl_sync(0xffffffffu, idx, 16 + j0 + j);
            s[j]   = __shfl_sync(0xffffffffu, idx, j0 + j);
            v[j] = __ldg((const float4*)(X + (size_t)dj * D) + lane);
        }
        #pragma unroll
        for (int j = 0; j < 8; j++) {
            float* p = g_nbr_sum + (size_t)s[j] * D + lane * 4;
            asm volatile("red.global.add.v4.f32 [%0], {%1,%2,%3,%4};"
                         :: "l"(p), "f"(v[j].x), "f"(v[j].y),
                            "f"(v[j].z), "f"(v[j].w) : "memory");
        }
    }
}

// ---------------------------------------------------------------------------
// Kernel 3: fused dual TF32 GEMM:  out = X @ Ws + tanh(S @ Wn + b)
// 128x128 CTA tile, 8 warps (4m x 2n), warp tile 32x64, m16n8k8.tf32.
// Fragments fed via ldmatrix.b16 (tf32 m16k8 fragment == f16 m16k16 pattern).
// Two K-passes share one accumulator; tanh between passes; single store.
// ---------------------------------------------------------------------------
__device__ __forceinline__ uint32_t f2tf32(float f) {
    uint32_t u;
    asm("cvt.rna.tf32.f32 %0, %1;" : "=r"(u) : "f"(f));
    return u;
}

#define LDSM4(r, addr)                                                        \
    asm volatile("ldmatrix.sync.aligned.m8n8.x4.shared.b16 "                  \
                 "{%0,%1,%2,%3}, [%4];"                                       \
                 : "=r"((r)[0]), "=r"((r)[1]), "=r"((r)[2]), "=r"((r)[3])     \
                 : "r"(addr))

#define MMA_TF32(c, a, b0, b1)                                                \
    asm volatile("mma.sync.aligned.m16n8k8.row.col.f32.tf32.tf32.f32 "        \
                 "{%0,%1,%2,%3}, {%4,%5,%6,%7}, {%8,%9}, {%0,%1,%2,%3};"      \
                 : "+f"((c)[0]), "+f"((c)[1]), "+f"((c)[2]), "+f"((c)[3])     \
                 : "r"((a)[0]), "r"((a)[1]), "r"((a)[2]), "r"((a)[3]),        \
                   "r"(b0), "r"(b1))

__global__ __launch_bounds__(256, 2)
void dual_gemm_tf32_kernel(const float* __restrict__ X,
                           const float* __restrict__ Ws,
                           const float* __restrict__ Wn,
                           const float* __restrict__ bias,
                           float* __restrict__ out,
                           int M) {
    __shared__ uint32_t As[128][36];   // [m][k], pad 36: conflict-free LDSM
    __shared__ uint32_t Bs[128][36];   // [n][k] (transposed), pad 36

    const int tid  = threadIdx.x;
    const int m0   = blockIdx.x * 128;
    const int warp = tid >> 5;
    const int lane = tid & 31;
    const int wm   = warp & 3;    // m offset wm*32
    const int wn   = warp >> 2;   // n offset wn*64
    const int g    = lane >> 2;
    const int t    = lane & 3;
    const int q    = lane >> 3;   // ldmatrix tile selector
    const int r8   = lane & 7;    // ldmatrix row within tile

    // ldmatrix per-lane base addresses (byte, shared space)
    uint32_t as_base = (uint32_t)__cvta_generic_to_shared(&As[0][0]);
    uint32_t bs_base = (uint32_t)__cvta_generic_to_shared(&Bs[0][0]);
    uint32_t aAddr[2], bAddr[4];
    #pragma unroll
    for (int im = 0; im < 2; im++)
        aAddr[im] = as_base +
            (((wm * 32 + im * 16 + (q & 1) * 8 + r8) * 36 + (q >> 1) * 4) << 2);
    #pragma unroll
    for (int jj = 0; jj < 4; jj++)
        bAddr[jj] = bs_base +
            (((wn * 64 + jj * 16 + (q >> 1) * 8 + r8) * 36 + (q & 1) * 4) << 2);

    float c[2][8][4];
    #pragma unroll
    for (int im = 0; im < 2; im++)
        #pragma unroll
        for (int n_ = 0; n_ < 8; n_++)
            #pragma unroll
            for (int x = 0; x < 4; x++) c[im][n_][x] = 0.f;

    #pragma unroll 1
    for (int pass = 0; pass < 2; pass++) {
        const float* Ap = pass ? X  : g_nbr_sum;
        const float* Bp = pass ? Ws : Wn;

        #pragma unroll 1
        for (int k0 = 0; k0 < 128; k0 += 32) {
            __syncthreads();
            // --- stage A [m][k]: 128x32, coalesced float4 reads
            #pragma unroll
            for (int l = 0; l < 4; l++) {
                int v = tid + l * 256;
                int row = v >> 3, c4 = v & 7;
                int gr = m0 + row;
                if (gr > M - 1) gr = M - 1;
                float4 a = __ldg((const float4*)(Ap + (size_t)gr * 128 + k0) + c4);
                uint32_t* p = &As[row][c4 * 4];
                p[0] = f2tf32(a.x); p[1] = f2tf32(a.y);
                p[2] = f2tf32(a.z); p[3] = f2tf32(a.w);
            }
            // --- stage B transposed [n][k]: warp = 32 k's for fixed n4
            //     (writes hit all 32 banks; reads are L2-hot weights)
            #pragma unroll
            for (int l = 0; l < 4; l++) {
                int v = tid + l * 256;
                int k = v & 31, n4 = v >> 5;
                float4 b = __ldg((const float4*)(Bp + (size_t)(k0 + k) * 128) + n4);
                Bs[n4 * 4 + 0][k] = f2tf32(b.x);
                Bs[n4 * 4 + 1][k] = f2tf32(b.y);
                Bs[n4 * 4 + 2][k] = f2tf32(b.z);
                Bs[n4 * 4 + 3][k] = f2tf32(b.w);
            }
            __syncthreads();

            #pragma unroll
            for (int kk = 0; kk < 32; kk += 8) {
                uint32_t af[2][4];
                LDSM4(af[0], aAddr[0] + kk * 4);
                LDSM4(af[1], aAddr[1] + kk * 4);
                #pragma unroll
                for (int jj = 0; jj < 4; jj++) {
                    uint32_t bf[4];
                    LDSM4(bf, bAddr[jj] + kk * 4);
                    MMA_TF32(c[0][2 * jj],     af[0], bf[0], bf[1]);
                    MMA_TF32(c[0][2 * jj + 1], af[0], bf[2], bf[3]);
                    MMA_TF32(c[1][2 * jj],     af[1], bf[0], bf[1]);
                    MMA_TF32(c[1][2 * jj + 1], af[1], bf[2], bf[3]);
                }
            }
        }

        if (pass == 0) {
            // epilogue of GEMM 1: c = tanh(c + bias[col])
            #pragma unroll
            for (int n_ = 0; n_ < 8; n_++) {
                int col = wn * 64 + n_ * 8 + 2 * t;
                float b0 = __ldg(bias + col);
                float b1 = __ldg(bias + col + 1);
                #pragma unroll
                for (int im = 0; im < 2; im++) {
                    c[im][n_][0] = tanhf(c[im][n_][0] + b0);
                    c[im][n_][1] = tanhf(c[im][n_][1] + b1);
                    c[im][n_][2] = tanhf(c[im][n_][2] + b0);
                    c[im][n_][3] = tanhf(c[im][n_][3] + b1);
                }
            }
        }
    }

    // --- single store of out
    #pragma unroll
    for (int im = 0; im < 2; im++) {
        int r0 = m0 + wm * 32 + im * 16 + g;
        #pragma unroll
        for (int n_ = 0; n_ < 8; n_++) {
            int col = wn * 64 + n_ * 8 + 2 * t;
            if (r0 < M) {
                float2* p = (float2*)(out + (size_t)r0 * 128 + col);
                *p = make_float2(c[im][n_][0], c[im][n_][1]);
            }
            if (r0 + 8 < M) {
                float2* p = (float2*)(out + (size_t)(r0 + 8) * 128 + col);
                *p = make_float2(c[im][n_][2], c[im][n_][3]);
            }
        }
    }
}

// ---------------------------------------------------------------------------
// Launch
// ---------------------------------------------------------------------------
extern "C" void kernel_launch(void* const* d_in, const int* in_sizes, int n_in,
                              void* d_out, int out_size) {
    const float* X   = (const float*)d_in[0];   // [N, 128]
    const void*  ei  = d_in[1];                 // [2, E] int32 or int64
    const float* Wn  = (const float*)d_in[2];   // nbr_w [128,128]
    const float* Ws  = (const float*)d_in[3];   // self_w [128,128]
    const float* b   = (const float*)d_in[4];   // [128]
    float*       out = (float*)d_out;

    const int M = in_sizes[0] / D;       // 50000
    const int E = in_sizes[1] / 2;       // 800000

    // 1) zero accumulator + sniff index dtype
    int n_f4 = (M * D) / 4;
    zero_sniff_kernel<<<(n_f4 + 255) / 256, 256>>>((const unsigned*)ei, n_f4);

    // 2) scatter (full occupancy, 16 edges/warp)
    int s_blocks = (E + 127) / 128;
    scatter_kernel<<<s_blocks, 256>>>(X, ei, E);

    // 3) fused dual TF32 GEMM + tanh
    int g_blocks = (M + 127) / 128;
    dual_gemm_tf32_kernel<<<g_blocks, 256>>>(X, Ws, Wn, b, out, M);
}